// round 14
// baseline (speedup 1.0000x reference)
#include <cuda_runtime.h>
#include <cstddef>

#define EDIM    1024
#define BLK     256
#define SLICE   8                // floats of e-dim owned per block (32 B)
#define NSLICES (EDIM / SLICE)   // 128
#define GRID    2048
#define GROUPS  (GRID / NSLICES) // 16 token groups

// ---------------------------------------------------------------------------
// Single kernel, zero inter-block synchronization (R8 structure, SLICE=8).
// Block bid: slice s = bid & 127 (e-range [8s, 8s+8)), group g = bid >> 7.
//  1) compute z[0..1023] into smem (4 wires/thread; amplitude algebra,
//     fast trig -- formulation verified at rel_err 1.09e-6)
//  2) y_s[r] = W[8s+r,:] . z + b[8s+r] for r = 0..7 (one warp per row)
//  3) stream its 32 B slice to every token in its group (2 threads/token,
//     16 B each, .cs streaming stores; 32 B = one DRAM sector)
// SLICE=8 halves chip-wide W L2-read traffic (128->64 MB) vs SLICE=16 at the
// same grid/trig, relieving LTS pressure (~79% -> ~66% of cap).
// ---------------------------------------------------------------------------
__global__ void __launch_bounds__(BLK)
fused_kernel(const float* __restrict__ bs_theta,
             const float* __restrict__ bs_phi,
             const float* __restrict__ phases,
             const float* __restrict__ squeeze_r,
             const float* __restrict__ disp_r,
             const float* __restrict__ W,
             const float* __restrict__ bvec,
             float* __restrict__ out, size_t n_tokens) {
    const int tid = threadIdx.x;
    const int s   = blockIdx.x & (NSLICES - 1);
    const int g   = blockIdx.x >> 7;

    __shared__ float zsh[EDIM];
    __shared__ float ysh[SLICE];

    // ---- 1) z into smem: 4 wires per thread, amplitude algebra ----
    float c0, s0, c1, s1;
    __sincosf(0.5f * bs_theta[0], &s0, &c0);
    __sincosf(0.5f * bs_phi[0],   &s1, &c1);

    #pragma unroll
    for (int kk = 0; kk < EDIM / BLK; kk++) {
        const int e = tid + BLK * kk;
        float ar = 1.f, ai = 0.f, br = 0.f, bi = 0.f;
        // rx(bs_theta): a' = c*a - i*s*b ; b' = -i*s*a + c*b
        {
            float nar =  c0 * ar + s0 * bi;
            float nai =  c0 * ai - s0 * br;
            float nbr =  s0 * ai + c0 * br;
            float nbi = -s0 * ar + c0 * bi;
            ar = nar; ai = nai; br = nbr; bi = nbi;
        }
        // ry(bs_phi)
        {
            float nar = c1 * ar - s1 * br;
            float nai = c1 * ai - s1 * bi;
            float nbr = s1 * ar + c1 * br;
            float nbi = s1 * ai + c1 * bi;
            ar = nar; ai = nai; br = nbr; bi = nbi;
        }
        // rz(phases[e])
        {
            float cp, sp;
            __sincosf(0.5f * phases[e], &sp, &cp);
            float nar = cp * ar + sp * ai;
            float nai = cp * ai - sp * ar;
            float nbr = cp * br - sp * bi;
            float nbi = cp * bi + sp * br;
            ar = nar; ai = nai; br = nbr; bi = nbi;
        }
        // ry(squeeze_r[e])
        {
            float c, ss;
            __sincosf(0.5f * squeeze_r[e], &ss, &c);
            float nar = c * ar - ss * br;
            float nai = c * ai - ss * bi;
            float nbr = ss * ar + c * br;
            float nbi = ss * ai + c * bi;
            ar = nar; ai = nai; br = nbr; bi = nbi;
        }
        // rx(displacement_r[e])
        {
            float c, ss;
            __sincosf(0.5f * disp_r[e], &ss, &c);
            float nar =  c * ar + ss * bi;
            float nai =  c * ai - ss * br;
            float nbr =  ss * ai + c * br;
            float nbi = -ss * ar + c * bi;
            ar = nar; ai = nai; br = nbr; bi = nbi;
        }
        // rz(kerr) rotates phases only -> |amp|^2 unchanged. Dropped.
        zsh[e] = (ar * ar + ai * ai) - (br * br + bi * bi);
    }
    __syncthreads();

    // ---- 2) y for this slice: 8 rows, one warp per row ----
    {
        const int row = tid >> 5;          // 0..7  (= warp id)
        const int lr  = tid & 31;          // lane
        const int f   = s * SLICE + row;
        const float4* __restrict__ wrow =
            reinterpret_cast<const float4*>(W + (size_t)f * EDIM);
        const float4* __restrict__ z4 = reinterpret_cast<const float4*>(zsh);

        float p = 0.f;
        #pragma unroll
        for (int q = 0; q < 8; q++) {
            float4 w = __ldg(&wrow[lr + 32 * q]);
            float4 z = z4[lr + 32 * q];
            p += w.x * z.x + w.y * z.y + w.z * z.z + w.w * z.w;
        }
        // full-warp reduction -> lane 0
        #pragma unroll
        for (int o = 16; o > 0; o >>= 1)
            p += __shfl_down_sync(0xffffffffu, p, o);
        if (lr == 0) ysh[row] = p + bvec[f];
    }
    __syncthreads();

    // ---- 3) stream this 32 B slice to all tokens in group g ----
    // 2 threads per token, 16 B each; 128 tokens per iteration.
    const int pair = tid & 1;
    const float4 v = *reinterpret_cast<const float4*>(&ysh[pair * 4]);

    const size_t tpg        = n_tokens / GROUPS;           // 4096
    const size_t base_token = (size_t)g * tpg;
    const size_t end_token  = base_token + tpg;

    float* p0 = out + (base_token + (tid >> 1)) * EDIM + s * SLICE + pair * 4;
    const size_t step = (size_t)128 * EDIM;    // 128 tokens per iteration

    size_t t = base_token + (tid >> 1);
    for (; t + 3 * 128 < end_token; t += 4 * 128) {
        __stcs(reinterpret_cast<float4*>(p0), v);
        __stcs(reinterpret_cast<float4*>(p0 + step), v);
        __stcs(reinterpret_cast<float4*>(p0 + 2 * step), v);
        __stcs(reinterpret_cast<float4*>(p0 + 3 * step), v);
        p0 += 4 * step;
    }
    for (; t < end_token; t += 128) {
        __stcs(reinterpret_cast<float4*>(p0), v);
        p0 += step;
    }
}

// ---------------------------------------------------------------------------
// Inputs (metadata order):
//   0: x (B,S,E) f32        -- UNUSED (output is x-independent)
//   1: bs_theta (1,) f32
//   2: bs_phi   (1,) f32
//   3: phases   (E,) f32
//   4: squeeze_r(E,) f32
//   5: displacement_r (E,) f32
//   6: kerr     (E,) f32    -- UNUSED (rz does not change |amp|^2)
//   7: W_combine (E,E) f32
//   8: b_combine (E,) f32
// Output: (B,S,E) f32, B*S = 65536 tokens
// ---------------------------------------------------------------------------
extern "C" void kernel_launch(void* const* d_in, const int* in_sizes, int n_in,
                              void* d_out, int out_size) {
    const float* bs_theta = (const float*)d_in[1];
    const float* bs_phi   = (const float*)d_in[2];
    const float* phases   = (const float*)d_in[3];
    const float* squeeze  = (const float*)d_in[4];
    const float* disp     = (const float*)d_in[5];
    const float* W        = (const float*)d_in[7];
    const float* bvec     = (const float*)d_in[8];

    const size_t n_tokens = (size_t)out_size / EDIM;   // 65536

    fused_kernel<<<GRID, BLK>>>(bs_theta, bs_phi, phases, squeeze, disp,
                                W, bvec, (float*)d_out, n_tokens);
}

// round 15
// speedup vs baseline: 1.2284x; 1.2284x over previous
#include <cuda_runtime.h>
#include <cstddef>

#define EDIM    1024
#define BLK     256
#define SLICE   16               // floats of e-dim owned per block (64 B)
#define NSLICES (EDIM / SLICE)   // 64
#define GRID    2048
#define GROUPS  (GRID / NSLICES) // 32 token groups

// ---------------------------------------------------------------------------
// Single kernel, zero inter-block synchronization — the measured optimum:
// {GRID 2048, BLK 256, SLICE 16 (64 B store chunks), .cs streaming stores}.
// Block bid: slice s = bid & 63 (e-range [16s, 16s+16)), group g = bid >> 6.
//  1) compute z[0..1023] into smem (4 wires/thread; amplitude algebra,
//     fast trig -- formulation verified at rel_err 1.09e-6)
//  2) y_s[r] = W[16s+r,:] . z + b[16s+r]  for r = 0..15  (16 threads/row)
//  3) stream its 64 B slice to every token in its group (4 threads/token,
//     16 B each, 8-deep unrolled .cs stores)
// ---------------------------------------------------------------------------
__global__ void __launch_bounds__(BLK)
fused_kernel(const float* __restrict__ bs_theta,
             const float* __restrict__ bs_phi,
             const float* __restrict__ phases,
             const float* __restrict__ squeeze_r,
             const float* __restrict__ disp_r,
             const float* __restrict__ W,
             const float* __restrict__ bvec,
             float* __restrict__ out, size_t n_tokens) {
    const int tid = threadIdx.x;
    const int s   = blockIdx.x & (NSLICES - 1);
    const int g   = blockIdx.x >> 6;

    __shared__ float zsh[EDIM];
    __shared__ float ysh[SLICE];

    // ---- 1) z into smem: 4 wires per thread, amplitude algebra ----
    float c0, s0, c1, s1;
    __sincosf(0.5f * bs_theta[0], &s0, &c0);
    __sincosf(0.5f * bs_phi[0],   &s1, &c1);

    #pragma unroll
    for (int kk = 0; kk < EDIM / BLK; kk++) {
        const int e = tid + BLK * kk;
        float ar = 1.f, ai = 0.f, br = 0.f, bi = 0.f;
        // rx(bs_theta): a' = c*a - i*s*b ; b' = -i*s*a + c*b
        {
            float nar =  c0 * ar + s0 * bi;
            float nai =  c0 * ai - s0 * br;
            float nbr =  s0 * ai + c0 * br;
            float nbi = -s0 * ar + c0 * bi;
            ar = nar; ai = nai; br = nbr; bi = nbi;
        }
        // ry(bs_phi)
        {
            float nar = c1 * ar - s1 * br;
            float nai = c1 * ai - s1 * bi;
            float nbr = s1 * ar + c1 * br;
            float nbi = s1 * ai + c1 * bi;
            ar = nar; ai = nai; br = nbr; bi = nbi;
        }
        // rz(phases[e])
        {
            float cp, sp;
            __sincosf(0.5f * phases[e], &sp, &cp);
            float nar = cp * ar + sp * ai;
            float nai = cp * ai - sp * ar;
            float nbr = cp * br - sp * bi;
            float nbi = cp * bi + sp * br;
            ar = nar; ai = nai; br = nbr; bi = nbi;
        }
        // ry(squeeze_r[e])
        {
            float c, ss;
            __sincosf(0.5f * squeeze_r[e], &ss, &c);
            float nar = c * ar - ss * br;
            float nai = c * ai - ss * bi;
            float nbr = ss * ar + c * br;
            float nbi = ss * ai + c * bi;
            ar = nar; ai = nai; br = nbr; bi = nbi;
        }
        // rx(displacement_r[e])
        {
            float c, ss;
            __sincosf(0.5f * disp_r[e], &ss, &c);
            float nar =  c * ar + ss * bi;
            float nai =  c * ai - ss * br;
            float nbr =  ss * ai + c * br;
            float nbi = -ss * ar + c * bi;
            ar = nar; ai = nai; br = nbr; bi = nbi;
        }
        // rz(kerr) rotates phases only -> |amp|^2 unchanged. Dropped.
        zsh[e] = (ar * ar + ai * ai) - (br * br + bi * bi);
    }
    __syncthreads();

    // ---- 2) y for this slice: 16 rows, 16 threads/row ----
    {
        const int row = tid >> 4;          // 0..15
        const int lr  = tid & 15;          // lane within row
        const int f   = s * SLICE + row;
        const float4* __restrict__ wrow =
            reinterpret_cast<const float4*>(W + (size_t)f * EDIM);
        const float4* __restrict__ z4 = reinterpret_cast<const float4*>(zsh);

        float p = 0.f;
        #pragma unroll
        for (int q = 0; q < 16; q++) {
            float4 w = __ldg(&wrow[lr + 16 * q]);
            float4 z = z4[lr + 16 * q];
            p += w.x * z.x + w.y * z.y + w.z * z.z + w.w * z.w;
        }
        // reduce across the 16 lanes of this row
        #pragma unroll
        for (int o = 8; o > 0; o >>= 1)
            p += __shfl_down_sync(0xffffffffu, p, o, 16);
        if (lr == 0) ysh[row] = p + bvec[f];
    }
    __syncthreads();

    // ---- 3) stream this slice to all tokens in group g ----
    // 4 threads per token, 16 B each; 64 tokens per iteration; unroll x8.
    const int quad = tid & 3;
    const float4 v = *reinterpret_cast<const float4*>(&ysh[quad * 4]);

    const size_t tpg        = n_tokens / GROUPS;           // 2048
    const size_t base_token = (size_t)g * tpg;
    const size_t end_token  = base_token + tpg;

    float* p0 = out + (base_token + (tid >> 2)) * EDIM + s * SLICE + quad * 4;
    const size_t step = (size_t)64 * EDIM;     // 64 tokens per iteration

    size_t t = base_token + (tid >> 2);
    for (; t + 7 * 64 < end_token; t += 8 * 64) {
        __stcs(reinterpret_cast<float4*>(p0), v);
        __stcs(reinterpret_cast<float4*>(p0 + step), v);
        __stcs(reinterpret_cast<float4*>(p0 + 2 * step), v);
        __stcs(reinterpret_cast<float4*>(p0 + 3 * step), v);
        __stcs(reinterpret_cast<float4*>(p0 + 4 * step), v);
        __stcs(reinterpret_cast<float4*>(p0 + 5 * step), v);
        __stcs(reinterpret_cast<float4*>(p0 + 6 * step), v);
        __stcs(reinterpret_cast<float4*>(p0 + 7 * step), v);
        p0 += 8 * step;
    }
    for (; t < end_token; t += 64) {
        __stcs(reinterpret_cast<float4*>(p0), v);
        p0 += step;
    }
}

// ---------------------------------------------------------------------------
// Inputs (metadata order):
//   0: x (B,S,E) f32        -- UNUSED (output is x-independent)
//   1: bs_theta (1,) f32
//   2: bs_phi   (1,) f32
//   3: phases   (E,) f32
//   4: squeeze_r(E,) f32
//   5: displacement_r (E,) f32
//   6: kerr     (E,) f32    -- UNUSED (rz does not change |amp|^2)
//   7: W_combine (E,E) f32
//   8: b_combine (E,) f32
// Output: (B,S,E) f32, B*S = 65536 tokens
// ---------------------------------------------------------------------------
extern "C" void kernel_launch(void* const* d_in, const int* in_sizes, int n_in,
                              void* d_out, int out_size) {
    const float* bs_theta = (const float*)d_in[1];
    const float* bs_phi   = (const float*)d_in[2];
    const float* phases   = (const float*)d_in[3];
    const float* squeeze  = (const float*)d_in[4];
    const float* disp     = (const float*)d_in[5];
    const float* W        = (const float*)d_in[7];
    const float* bvec     = (const float*)d_in[8];

    const size_t n_tokens = (size_t)out_size / EDIM;   // 65536

    fused_kernel<<<GRID, BLK>>>(bs_theta, bs_phi, phases, squeeze, disp,
                                W, bvec, (float*)d_out, n_tokens);
}